// round 1
// baseline (speedup 1.0000x reference)
#include <cuda_runtime.h>
#include <cstdint>

// ----------------------------------------------------------------------------
// Problem constants
// ----------------------------------------------------------------------------
#define BATCH     64
#define HW        16
#define L_SEQ     256
#define IN_IMG    512
#define IN_PC     256
#define COMB      770
#define DIM       128
#define D_MODEL   1282
#define D_INNER   2564
#define D_STATE   16
#define D_CONV    4
#define DT_RANK   81
#define XPROJ_N   113
#define M_TOTAL   (BATCH * L_SEQ)      // 16384

#define POOL5_OFF   0
#define POOL9_OFF   1600
#define POOL13_OFF  6784
#define POOL_ROWS   17600

// ----------------------------------------------------------------------------
// Device scratch (static — no cudaMalloc allowed)
// ----------------------------------------------------------------------------
__device__ float g_seq   [(size_t)M_TOTAL * D_MODEL];
__device__ float g_comb  [(size_t)BATCH * COMB * L_SEQ];
__device__ float g_xz    [(size_t)M_TOTAL * 2 * D_INNER];
__device__ float g_uact  [(size_t)M_TOTAL * D_INNER];
__device__ float g_dbl   [(size_t)M_TOTAL * XPROJ_N];
__device__ float g_dt    [(size_t)M_TOTAL * D_INNER];
__device__ float g_y     [(size_t)M_TOTAL * D_INNER];
__device__ float g_yo    [(size_t)M_TOTAL * D_MODEL];
__device__ float g_p0    [(size_t)M_TOTAL * DIM];
__device__ float g_y0    [BATCH * DIM];
__device__ float g_pooled[(size_t)POOL_ROWS * COMB];
__device__ float g_ys    [(size_t)POOL_ROWS * DIM];
__device__ float g_bninv [4 * DIM];
__device__ float g_bnbias[4 * DIM];

// ----------------------------------------------------------------------------
__global__ void prep_bn_kernel(const float* __restrict__ gamma,
                               const float* __restrict__ beta,
                               const float* __restrict__ mean,
                               const float* __restrict__ var) {
    int i = blockIdx.x * 256 + threadIdx.x;
    if (i < 4 * DIM) {
        float iv = rsqrtf(var[i] + 1e-5f) * gamma[i];
        g_bninv[i]  = iv;
        g_bnbias[i] = beta[i] - mean[i] * iv;
    }
}

// ----------------------------------------------------------------------------
__global__ void build_comb_kernel(const float* __restrict__ x,
                                  const float* __restrict__ pc) {
    size_t idx = (size_t)blockIdx.x * 256 + threadIdx.x;
    if (idx >= (size_t)BATCH * COMB * L_SEQ) return;
    int l = (int)(idx % L_SEQ);
    int c = (int)((idx / L_SEQ) % COMB);
    int b = (int)(idx / ((size_t)L_SEQ * COMB));
    float v;
    if (c < IN_IMG) {
        v = x[((size_t)(b * IN_IMG + c)) * L_SEQ + l];
    } else if (c == IN_IMG) {          // meshgrid X: xx[w]
        int w = l & 15;
        v = -0.3f + 0.6f * (float)w / 15.0f;
    } else if (c == IN_IMG + 1) {      // meshgrid Y: xx[h]
        int h = l >> 4;
        v = -0.3f + 0.6f * (float)h / 15.0f;
    } else {
        v = pc[b * IN_PC + (c - IN_IMG - 2)];
    }
    g_comb[((size_t)(b * COMB + c)) * L_SEQ + l] = v;
    g_seq[((size_t)(b * L_SEQ + l)) * D_MODEL + c] = v;
}

// ----------------------------------------------------------------------------
__global__ void pool_avg_kernel() {
    __shared__ float s[32][257];
    int b  = blockIdx.y;
    int c0 = blockIdx.x * 32;
    int tid = threadIdx.x;
    for (int i = tid; i < 32 * 256; i += 256) {
        int cl = i >> 8, l = i & 255;
        int c = c0 + cl;
        s[cl][l] = (c < COMB) ? g_comb[((size_t)(b * COMB + c)) * L_SEQ + l] : 0.f;
    }
    __syncthreads();
    for (int oidx = tid; oidx < 275 * 32; oidx += 256) {
        int cl = oidx & 31;
        int q  = oidx >> 5;
        int sdim, qb, base;
        if (q < 25)       { sdim = 5;  qb = q;       base = POOL5_OFF;  }
        else if (q < 106) { sdim = 9;  qb = q - 25;  base = POOL9_OFF;  }
        else              { sdim = 13; qb = q - 106; base = POOL13_OFF; }
        int o = qb / sdim, p = qb % sdim;
        int h0 = (o * 16) / sdim, h1 = ((o + 1) * 16 + sdim - 1) / sdim;
        int w0 = (p * 16) / sdim, w1 = ((p + 1) * 16 + sdim - 1) / sdim;
        float sum = 0.f;
        for (int h = h0; h < h1; h++)
            for (int w = w0; w < w1; w++)
                sum += s[cl][h * 16 + w];
        sum *= 1.0f / (float)((h1 - h0) * (w1 - w0));
        int c = c0 + cl;
        if (c < COMB)
            g_pooled[((size_t)(base + b * sdim * sdim + qb)) * COMB + c] = sum;
    }
}

// ----------------------------------------------------------------------------
// Generic tiled fp32 GEMM: C[m,n] = sum_k A[m*lda+k] * W[n*ldw+k]
// EPI 0: none   EPI 1: BN+ReLU6   EPI 2: softplus(v + eb[n])
// ----------------------------------------------------------------------------
#define GBM 128
#define GBN 128
#define GBK 16

template <int EPI>
__global__ __launch_bounds__(256, 2)
void gemm_kernel(const float* __restrict__ A, int lda,
                 const float* __restrict__ Wt, int ldw,
                 float* __restrict__ C, int ldc,
                 int M, int N, int K,
                 const float* __restrict__ ea, const float* __restrict__ eb) {
    __shared__ float sA[GBK][GBM + 4];
    __shared__ float sB[GBK][GBN + 4];
    int tid = threadIdx.x;
    int bm = blockIdx.y * GBM;
    int bn = blockIdx.x * GBN;
    int tx = tid & 15, ty = tid >> 4;
    float acc[8][8];
    #pragma unroll
    for (int i = 0; i < 8; i++)
        #pragma unroll
        for (int j = 0; j < 8; j++) acc[i][j] = 0.f;

    for (int k0 = 0; k0 < K; k0 += GBK) {
        #pragma unroll
        for (int i = 0; i < 8; i++) {
            int e = tid + i * 256;
            int r = e >> 4, c = e & 15;
            int gm = bm + r, gk = k0 + c;
            sA[c][r] = (gm < M && gk < K) ? A[(size_t)gm * lda + gk] : 0.f;
        }
        #pragma unroll
        for (int i = 0; i < 8; i++) {
            int e = tid + i * 256;
            int r = e >> 4, c = e & 15;
            int gn = bn + r, gk = k0 + c;
            sB[c][r] = (gn < N && gk < K) ? Wt[(size_t)gn * ldw + gk] : 0.f;
        }
        __syncthreads();
        #pragma unroll
        for (int kk = 0; kk < GBK; kk++) {
            float a[8], bb[8];
            #pragma unroll
            for (int i = 0; i < 8; i++) a[i]  = sA[kk][ty * 8 + i];
            #pragma unroll
            for (int i = 0; i < 8; i++) bb[i] = sB[kk][tx * 8 + i];
            #pragma unroll
            for (int i = 0; i < 8; i++)
                #pragma unroll
                for (int j = 0; j < 8; j++)
                    acc[i][j] = fmaf(a[i], bb[j], acc[i][j]);
        }
        __syncthreads();
    }

    #pragma unroll
    for (int i = 0; i < 8; i++) {
        int gm = bm + ty * 8 + i;
        if (gm >= M) continue;
        #pragma unroll
        for (int j = 0; j < 8; j++) {
            int gn = bn + tx * 8 + j;
            if (gn >= N) continue;
            float v = acc[i][j];
            if (EPI == 1) {
                v = v * ea[gn] + eb[gn];
                v = fminf(fmaxf(v, 0.f), 6.f);
            } else if (EPI == 2) {
                v = v + eb[gn];
                v = (v > 20.f) ? v : log1pf(expf(v));
            }
            C[(size_t)gm * ldc + gn] = v;
        }
    }
}

// ----------------------------------------------------------------------------
__global__ void pool0_mean_kernel() {
    int b = blockIdx.x;
    int d = threadIdx.x;
    float s = 0.f;
    for (int l = 0; l < L_SEQ; l++)
        s += g_p0[((size_t)(b * L_SEQ + l)) * DIM + d];
    g_y0[b * DIM + d] = s * (1.0f / (float)L_SEQ);
}

// ----------------------------------------------------------------------------
__global__ void fill_pool_cols_kernel() {
    int m = blockIdx.x;
    int t = threadIdx.x;
    int b = m >> 8, l = m & 255;
    int h = l >> 4, w = l & 15;
    int si = t >> 7, d = t & 127;
    float v;
    if (si == 0) {
        v = g_y0[b * DIM + d];
    } else {
        int sdim = (si == 1) ? 5 : (si == 2) ? 9 : 13;
        int base = (si == 1) ? POOL5_OFF : (si == 2) ? POOL9_OFF : POOL13_OFF;
        float sh = (h + 0.5f) * (float)sdim / 16.0f - 0.5f;
        sh = fminf(fmaxf(sh, 0.f), (float)sdim - 1.f);
        int h0 = (int)sh;
        int h1 = min(h0 + 1, sdim - 1);
        float fh = sh - (float)h0;
        float sw = (w + 0.5f) * (float)sdim / 16.0f - 0.5f;
        sw = fminf(fmaxf(sw, 0.f), (float)sdim - 1.f);
        int w0 = (int)sw;
        int w1 = min(w0 + 1, sdim - 1);
        float fw = sw - (float)w0;
        const float* Y = g_ys + (size_t)(base + b * sdim * sdim) * DIM;
        float v00 = Y[(size_t)(h0 * sdim + w0) * DIM + d];
        float v01 = Y[(size_t)(h0 * sdim + w1) * DIM + d];
        float v10 = Y[(size_t)(h1 * sdim + w0) * DIM + d];
        float v11 = Y[(size_t)(h1 * sdim + w1) * DIM + d];
        v = (1.f - fh) * ((1.f - fw) * v00 + fw * v01)
          +        fh  * ((1.f - fw) * v10 + fw * v11);
    }
    g_seq[(size_t)m * D_MODEL + COMB + t] = v;
}

// ----------------------------------------------------------------------------
__global__ void conv1d_silu_kernel(const float* __restrict__ w,
                                   const float* __restrict__ bias) {
    int d = blockIdx.x * 256 + threadIdx.x;
    int m = blockIdx.y;
    if (d >= D_INNER) return;
    int b = m >> 8, l = m & 255;
    float acc = bias[d];
    #pragma unroll
    for (int k = 0; k < D_CONV; k++) {
        int ls = l + k - (D_CONV - 1);
        if (ls >= 0)
            acc += w[d * D_CONV + k] * g_xz[((size_t)(b * L_SEQ + ls)) * (2 * D_INNER) + d];
    }
    float sg = 1.f / (1.f + __expf(-acc));
    g_uact[(size_t)m * D_INNER + d] = acc * sg;
}

// ----------------------------------------------------------------------------
__global__ __launch_bounds__(256)
void scan_kernel(const float* __restrict__ A_log, const float* __restrict__ Dp) {
    __shared__ float sB[L_SEQ][D_STATE];
    __shared__ float sC[L_SEQ][D_STATE];
    int b = blockIdx.y;
    int d = blockIdx.x * 256 + threadIdx.x;
    int tid = threadIdx.x;
    for (int i = tid; i < L_SEQ * D_STATE; i += 256) {
        int l = i >> 4, n = i & 15;
        const float* row = g_dbl + (size_t)(b * L_SEQ + l) * XPROJ_N;
        sB[l][n] = row[DT_RANK + n];
        sC[l][n] = row[DT_RANK + D_STATE + n];
    }
    __syncthreads();
    if (d >= D_INNER) return;

    float Ad[D_STATE];
    #pragma unroll
    for (int n = 0; n < D_STATE; n++) Ad[n] = -expf(A_log[d * D_STATE + n]);
    float Dd = Dp[d];
    float h[D_STATE];
    #pragma unroll
    for (int n = 0; n < D_STATE; n++) h[n] = 0.f;

    for (int l = 0; l < L_SEQ; l++) {
        size_t m = (size_t)(b * L_SEQ + l);
        float dt = g_dt[m * D_INNER + d];
        float u  = g_uact[m * D_INNER + d];
        float z  = g_xz[m * (2 * D_INNER) + D_INNER + d];
        float dtu = dt * u;
        float y = 0.f;
        #pragma unroll
        for (int n = 0; n < D_STATE; n++) {
            float dA = __expf(dt * Ad[n]);
            h[n] = dA * h[n] + dtu * sB[l][n];
            y = fmaf(h[n], sC[l][n], y);
        }
        float sig = 1.f / (1.f + __expf(-z));
        g_y[m * D_INNER + d] = (y + u * Dd) * (z * sig);
    }
}

// ----------------------------------------------------------------------------
__global__ void transpose_out_kernel(float* __restrict__ out) {
    __shared__ float s[32][33];
    int b  = blockIdx.z;
    int c0 = blockIdx.x * 32;
    int l0 = blockIdx.y * 32;
    int tx = threadIdx.x, ty = threadIdx.y;
    for (int i = ty; i < 32; i += 8) {
        int l = l0 + i, c = c0 + tx;
        s[i][tx] = (c < D_MODEL) ? g_yo[((size_t)(b * L_SEQ + l)) * D_MODEL + c] : 0.f;
    }
    __syncthreads();
    for (int i = ty; i < 32; i += 8) {
        int c = c0 + i, l = l0 + tx;
        if (c < D_MODEL)
            out[((size_t)(b * D_MODEL + c)) * L_SEQ + l] = s[tx][i];
    }
}

// ----------------------------------------------------------------------------
extern "C" void kernel_launch(void* const* d_in, const int* in_sizes, int n_in,
                              void* d_out, int out_size) {
    const float* x          = (const float*)d_in[0];
    const float* pc_emb     = (const float*)d_in[1];
    const float* conv_w     = (const float*)d_in[2];
    const float* bn_gamma   = (const float*)d_in[3];
    const float* bn_beta    = (const float*)d_in[4];
    const float* bn_mean    = (const float*)d_in[5];
    const float* bn_var     = (const float*)d_in[6];
    const float* in_proj_w  = (const float*)d_in[7];
    const float* conv1d_w   = (const float*)d_in[8];
    const float* conv1d_b   = (const float*)d_in[9];
    const float* x_proj_w   = (const float*)d_in[10];
    const float* dt_proj_w  = (const float*)d_in[11];
    const float* dt_proj_b  = (const float*)d_in[12];
    const float* A_log      = (const float*)d_in[13];
    const float* Dp         = (const float*)d_in[14];
    const float* out_proj_w = (const float*)d_in[15];
    float* out = (float*)d_out;

    float *p_seq, *p_xz, *p_uact, *p_dbl, *p_dt, *p_y, *p_yo, *p_p0, *p_pooled, *p_ys;
    float *p_bninv, *p_bnbias;
    cudaGetSymbolAddress((void**)&p_seq,    g_seq);
    cudaGetSymbolAddress((void**)&p_xz,     g_xz);
    cudaGetSymbolAddress((void**)&p_uact,   g_uact);
    cudaGetSymbolAddress((void**)&p_dbl,    g_dbl);
    cudaGetSymbolAddress((void**)&p_dt,     g_dt);
    cudaGetSymbolAddress((void**)&p_y,      g_y);
    cudaGetSymbolAddress((void**)&p_yo,     g_yo);
    cudaGetSymbolAddress((void**)&p_p0,     g_p0);
    cudaGetSymbolAddress((void**)&p_pooled, g_pooled);
    cudaGetSymbolAddress((void**)&p_ys,     g_ys);
    cudaGetSymbolAddress((void**)&p_bninv,  g_bninv);
    cudaGetSymbolAddress((void**)&p_bnbias, g_bnbias);

    // 1) fold BN
    prep_bn_kernel<<<2, 256>>>(bn_gamma, bn_beta, bn_mean, bn_var);

    // 2) build comb into (b,c,l) and seq layouts
    {
        size_t total = (size_t)BATCH * COMB * L_SEQ;
        build_comb_kernel<<<(unsigned)((total + 255) / 256), 256>>>(x, pc_emb);
    }

    // 3) adaptive pooling for scales 5/9/13
    pool_avg_kernel<<<dim3(25, BATCH), 256>>>();

    // 4) conv0 (full res) with BN+ReLU6
    gemm_kernel<1><<<dim3(1, M_TOTAL / GBM), 256>>>(
        p_seq, D_MODEL, conv_w, COMB, p_p0, DIM,
        M_TOTAL, DIM, COMB, p_bninv, p_bnbias);

    // 5) pool0 spatial mean
    pool0_mean_kernel<<<BATCH, DIM>>>();

    // 6) convs for scales 5/9/13
    {
        const int sM[3]   = {1600, 5184, 10816};
        const int sOff[3] = {POOL5_OFF, POOL9_OFF, POOL13_OFF};
        for (int i = 0; i < 3; i++) {
            int pool = i + 1;
            gemm_kernel<1><<<dim3(1, (sM[i] + GBM - 1) / GBM), 256>>>(
                p_pooled + (size_t)sOff[i] * COMB, COMB,
                conv_w + (size_t)pool * DIM * COMB, COMB,
                p_ys + (size_t)sOff[i] * DIM, DIM,
                sM[i], DIM, COMB,
                p_bninv + pool * DIM, p_bnbias + pool * DIM);
        }
    }

    // 7) fill seq columns [770, 1282)
    fill_pool_cols_kernel<<<M_TOTAL, 512>>>();

    // 8) in_proj GEMM -> g_xz
    gemm_kernel<0><<<dim3((2 * D_INNER + GBN - 1) / GBN, M_TOTAL / GBM), 256>>>(
        p_seq, D_MODEL, in_proj_w, D_MODEL, p_xz, 2 * D_INNER,
        M_TOTAL, 2 * D_INNER, D_MODEL, nullptr, nullptr);

    // 9) depthwise causal conv1d + SiLU
    conv1d_silu_kernel<<<dim3((D_INNER + 255) / 256, M_TOTAL), 256>>>(conv1d_w, conv1d_b);

    // 10) x_proj GEMM -> g_dbl (dt_raw | B | C)
    gemm_kernel<0><<<dim3(1, M_TOTAL / GBM), 256>>>(
        p_uact, D_INNER, x_proj_w, D_INNER, p_dbl, XPROJ_N,
        M_TOTAL, XPROJ_N, D_INNER, nullptr, nullptr);

    // 11) dt_proj GEMM with softplus(+bias) epilogue -> g_dt
    gemm_kernel<2><<<dim3((D_INNER + GBN - 1) / GBN, M_TOTAL / GBM), 256>>>(
        p_dbl, XPROJ_N, dt_proj_w, DT_RANK, p_dt, D_INNER,
        M_TOTAL, D_INNER, DT_RANK, nullptr, dt_proj_b);

    // 12) selective scan (fused output gate)
    scan_kernel<<<dim3((D_INNER + 255) / 256, BATCH), 256>>>(A_log, Dp);

    // 13) out_proj GEMM -> g_yo
    gemm_kernel<0><<<dim3((D_MODEL + GBN - 1) / GBN, M_TOTAL / GBM), 256>>>(
        p_y, D_INNER, out_proj_w, D_INNER, p_yo, D_MODEL,
        M_TOTAL, D_MODEL, D_INNER, nullptr, nullptr);

    // 14) transpose (b,l,c) -> (b,c,l)
    transpose_out_kernel<<<dim3((D_MODEL + 31) / 32, L_SEQ / 32, BATCH), dim3(32, 8)>>>(out);
}

// round 5
// speedup vs baseline: 2.0213x; 2.0213x over previous
#include <cuda_runtime.h>
#include <cuda_bf16.h>
#include <cstdint>

// ----------------------------------------------------------------------------
// Problem constants
// ----------------------------------------------------------------------------
#define BATCH     64
#define L_SEQ     256
#define IN_IMG    512
#define IN_PC     256
#define COMB      770
#define DIM       128
#define D_MODEL   1282
#define D_INNER   2564
#define D_STATE   16
#define D_CONV    4
#define DT_RANK   81
#define XPROJ_N   113
#define M_TOTAL   (BATCH * L_SEQ)      // 16384

#define POOL5_OFF   0
#define POOL9_OFF   1600
#define POOL13_OFF  6784
#define POOL_ROWS   17600

// ----------------------------------------------------------------------------
// Device scratch (static — same set as the known-good Round-1 kernel)
// ----------------------------------------------------------------------------
__device__ float g_seq   [(size_t)M_TOTAL * D_MODEL];
__device__ float g_comb  [(size_t)BATCH * COMB * L_SEQ];
__device__ float g_xz    [(size_t)M_TOTAL * 2 * D_INNER];
__device__ float g_uact  [(size_t)M_TOTAL * D_INNER];
__device__ float g_dbl   [(size_t)M_TOTAL * XPROJ_N];
__device__ float g_dt    [(size_t)M_TOTAL * D_INNER];
__device__ float g_y     [(size_t)M_TOTAL * D_INNER];
__device__ float g_p0    [(size_t)M_TOTAL * DIM];
__device__ float g_y0    [BATCH * DIM];
__device__ float g_pooled[(size_t)POOL_ROWS * COMB];
__device__ float g_ys    [(size_t)POOL_ROWS * DIM];
__device__ float g_bninv [4 * DIM];
__device__ float g_bnbias[4 * DIM];

// ----------------------------------------------------------------------------
// PTX helpers (baseline-ISA only: ldmatrix + mma.sync)
// ----------------------------------------------------------------------------
__device__ __forceinline__ uint32_t smem_to_u32(const void* p) {
    uint32_t a;
    asm("{ .reg .u64 t; cvta.to.shared.u64 t, %1; cvt.u32.u64 %0, t; }"
        : "=r"(a) : "l"(p));
    return a;
}
__device__ __forceinline__ void ldsm4(uint32_t* f, uint32_t addr) {
    asm volatile("ldmatrix.sync.aligned.m8n8.x4.shared.b16 {%0,%1,%2,%3}, [%4];"
                 : "=r"(f[0]), "=r"(f[1]), "=r"(f[2]), "=r"(f[3]) : "r"(addr));
}
__device__ __forceinline__ void mma16816(float* d, const uint32_t* a,
                                         uint32_t b0, uint32_t b1) {
    asm volatile(
        "mma.sync.aligned.m16n8k16.row.col.f32.bf16.bf16.f32 "
        "{%0,%1,%2,%3}, {%4,%5,%6,%7}, {%8,%9}, {%0,%1,%2,%3};"
        : "+f"(d[0]), "+f"(d[1]), "+f"(d[2]), "+f"(d[3])
        : "r"(a[0]), "r"(a[1]), "r"(a[2]), "r"(a[3]), "r"(b0), "r"(b1));
}

// fp32[8] -> bf16 hi uint4 + bf16 lo uint4
__device__ __forceinline__ void cvt_hilo(const float* v, uint4& hi, uint4& lo) {
    uint32_t h[4], l[4];
    #pragma unroll
    for (int i = 0; i < 4; i++) {
        __nv_bfloat16 h0 = __float2bfloat16(v[2*i]);
        __nv_bfloat16 h1 = __float2bfloat16(v[2*i+1]);
        float r0 = v[2*i]   - __bfloat162float(h0);
        float r1 = v[2*i+1] - __bfloat162float(h1);
        __nv_bfloat16 l0 = __float2bfloat16(r0);
        __nv_bfloat16 l1 = __float2bfloat16(r1);
        h[i] = (uint32_t)__bfloat16_as_ushort(h0) | ((uint32_t)__bfloat16_as_ushort(h1) << 16);
        l[i] = (uint32_t)__bfloat16_as_ushort(l0) | ((uint32_t)__bfloat16_as_ushort(l1) << 16);
    }
    hi = make_uint4(h[0], h[1], h[2], h[3]);
    lo = make_uint4(l[0], l[1], l[2], l[3]);
}

// ----------------------------------------------------------------------------
// HMMA bf16x3-split GEMM with in-register split:
//   C[m,n] = sum_k A[m,k] * Wt[n,k],  A/Wt fp32, accum fp32
// CTA 128x128, 8 warps (2m x 4n), warp 64x32, K-chunk 32, single-stage smem.
// EPI 0: plain fp32      EPI 1: transposed (b,c,l) final output
// EPI 3: softplus(v+eb[n])      EPI 4: BN+ReLU6 (v*ea[n]+eb[n], clip 0..6)
// ----------------------------------------------------------------------------
#define SOFF_AH 0
#define SOFF_AL 8192
#define SOFF_BH 16384
#define SOFF_BL 24576

template <int EPI>
__global__ __launch_bounds__(256)
void mma_gemm_kernel(const float* __restrict__ A, int lda,
                     const float* __restrict__ Wt, int ldw,
                     float* __restrict__ C, int ldc,
                     int M, int N, int K,
                     const float* __restrict__ ea, const float* __restrict__ eb) {
    __shared__ __align__(16) unsigned char smem_buf[34048];
    const uint32_t sbase = smem_to_u32(smem_buf);
    const int tid = threadIdx.x;
    const int lane = tid & 31, wid = tid >> 5;
    const int wm = wid >> 2, wn = wid & 3;
    const int bm = blockIdx.y * 128, bn = blockIdx.x * 128;
    const int nchunks = (K + 31) / 32;

    float acc[4][4][4];
    #pragma unroll
    for (int i = 0; i < 4; i++)
        #pragma unroll
        for (int j = 0; j < 4; j++)
            #pragma unroll
            for (int q = 0; q < 4; q++) acc[i][j][q] = 0.f;

    const int lrow = lane & 15;     // ldmatrix row within 16-row tile
    const int lkh  = lane >> 4;     // k-half select

    for (int ch = 0; ch < nchunks; ch++) {
        const int k0 = ch * 32;
        // ---- load + split + store: 512 16B units per matrix, 2 per thread ----
        #pragma unroll
        for (int uu = 0; uu < 2; uu++) {
            int u = tid + uu * 256;
            int r = u >> 2, cu = u & 3;
            uint32_t soff = (uint32_t)(r * 64 + ((cu ^ ((r >> 1) & 3)) << 4));
            int gk = k0 + cu * 8;
            float va[8];
            {
                const float* ap = A + (size_t)(bm + r) * lda + gk;
                bool arow = (bm + r) < M;
                #pragma unroll
                for (int i = 0; i < 8; i++)
                    va[i] = (arow && (gk + i) < K) ? ap[i] : 0.f;
            }
            uint4 hi, lo;
            cvt_hilo(va, hi, lo);
            *(uint4*)(smem_buf + SOFF_AH + soff) = hi;
            *(uint4*)(smem_buf + SOFF_AL + soff) = lo;
            {
                const float* bp = Wt + (size_t)(bn + r) * ldw + gk;
                bool brow = (bn + r) < N;
                #pragma unroll
                for (int i = 0; i < 8; i++)
                    va[i] = (brow && (gk + i) < K) ? bp[i] : 0.f;
            }
            cvt_hilo(va, hi, lo);
            *(uint4*)(smem_buf + SOFF_BH + soff) = hi;
            *(uint4*)(smem_buf + SOFF_BL + soff) = lo;
        }
        __syncthreads();
        // ---- mma over the 32-K chunk (two k16 steps) ----
        #pragma unroll
        for (int k16 = 0; k16 < 2; k16++) {
            const int cbase = k16 * 2 + lkh;
            uint32_t ahf[4][4], alf[4][4], bhf[4][2], blf[4][2];
            #pragma unroll
            for (int mi = 0; mi < 4; mi++) {
                int r = wm * 64 + mi * 16 + lrow;
                uint32_t off = (uint32_t)(r * 64 + ((cbase ^ ((r >> 1) & 3)) << 4));
                ldsm4(ahf[mi], sbase + SOFF_AH + off);
                ldsm4(alf[mi], sbase + SOFF_AL + off);
            }
            #pragma unroll
            for (int ni = 0; ni < 2; ni++) {
                int r = wn * 32 + ni * 16 + lrow;
                uint32_t off = (uint32_t)(r * 64 + ((cbase ^ ((r >> 1) & 3)) << 4));
                uint32_t bt[4];
                ldsm4(bt, sbase + SOFF_BH + off);
                bhf[ni * 2 + 0][0] = bt[0]; bhf[ni * 2 + 0][1] = bt[2];
                bhf[ni * 2 + 1][0] = bt[1]; bhf[ni * 2 + 1][1] = bt[3];
                ldsm4(bt, sbase + SOFF_BL + off);
                blf[ni * 2 + 0][0] = bt[0]; blf[ni * 2 + 0][1] = bt[2];
                blf[ni * 2 + 1][0] = bt[1]; blf[ni * 2 + 1][1] = bt[3];
            }
            #pragma unroll
            for (int mi = 0; mi < 4; mi++)
                #pragma unroll
                for (int nj = 0; nj < 4; nj++) {
                    mma16816(acc[mi][nj], ahf[mi], bhf[nj][0], bhf[nj][1]);
                    mma16816(acc[mi][nj], ahf[mi], blf[nj][0], blf[nj][1]);
                    mma16816(acc[mi][nj], alf[mi], bhf[nj][0], bhf[nj][1]);
                }
        }
        __syncthreads();
    }

    // ---- epilogue: two passes (warps wm==0 then wm==1) reusing tile smem ----
    const int m0 = bm + wm * 64, n0 = bn + wn * 32;
    const int tr = lane >> 2, tc2 = (lane & 3) * 2;
    #pragma unroll
    for (int pass = 0; pass < 2; pass++) {
        __syncthreads();
        if (wm == pass) {
            float* tp = (float*)(smem_buf + (size_t)wn * 8448);   // 64x33 floats
            #pragma unroll
            for (int mi = 0; mi < 4; mi++)
                #pragma unroll
                for (int nj = 0; nj < 4; nj++) {
                    int r0 = mi * 16 + tr, c0 = nj * 8 + tc2;
                    tp[r0 * 33 + c0]           = acc[mi][nj][0];
                    tp[r0 * 33 + c0 + 1]       = acc[mi][nj][1];
                    tp[(r0 + 8) * 33 + c0]     = acc[mi][nj][2];
                    tp[(r0 + 8) * 33 + c0 + 1] = acc[mi][nj][3];
                }
            __syncwarp();
            if (EPI == 0) {
                int gn = n0 + lane;
                if (gn < N)
                    for (int r = 0; r < 64; r++) {
                        int gm = m0 + r;
                        if (gm < M) C[(size_t)gm * ldc + gn] = tp[r * 33 + lane];
                    }
            } else if (EPI == 3) {
                int gn = n0 + lane;
                if (gn < N) {
                    float bias = eb[gn];
                    for (int r = 0; r < 64; r++) {
                        int gm = m0 + r;
                        if (gm >= M) break;
                        float v = tp[r * 33 + lane] + bias;
                        v = (v > 20.f) ? v : log1pf(expf(v));
                        C[(size_t)gm * ldc + gn] = v;
                    }
                }
            } else if (EPI == 4) {
                int gn = n0 + lane;
                if (gn < N) {
                    float sa = ea[gn], sb = eb[gn];
                    for (int r = 0; r < 64; r++) {
                        int gm = m0 + r;
                        if (gm >= M) break;
                        float v = tp[r * 33 + lane] * sa + sb;
                        v = fminf(fmaxf(v, 0.f), 6.f);
                        C[(size_t)gm * ldc + gn] = v;
                    }
                }
            } else {  // EPI 1: transposed final output (b, c, l); M == 16384
                for (int c = 0; c < 32; c++) {
                    int gn = n0 + c;
                    if (gn >= N) break;
                    int m = m0 + lane;
                    int b = m >> 8, l = m & 255;
                    C[((size_t)(b * D_MODEL + gn)) * L_SEQ + l] = tp[lane * 33 + c];
                    m = m0 + 32 + lane;
                    b = m >> 8; l = m & 255;
                    C[((size_t)(b * D_MODEL + gn)) * L_SEQ + l] = tp[(lane + 32) * 33 + c];
                }
            }
        }
    }
}

// ----------------------------------------------------------------------------
__global__ void prep_bn_kernel(const float* __restrict__ gamma,
                               const float* __restrict__ beta,
                               const float* __restrict__ mean,
                               const float* __restrict__ var) {
    int i = blockIdx.x * 256 + threadIdx.x;
    if (i < 4 * DIM) {
        float iv = rsqrtf(var[i] + 1e-5f) * gamma[i];
        g_bninv[i]  = iv;
        g_bnbias[i] = beta[i] - mean[i] * iv;
    }
}

// ----------------------------------------------------------------------------
__global__ void build_comb_kernel(const float* __restrict__ x,
                                  const float* __restrict__ pc) {
    size_t idx = (size_t)blockIdx.x * 256 + threadIdx.x;
    if (idx >= (size_t)BATCH * COMB * L_SEQ) return;
    int l = (int)(idx % L_SEQ);
    int c = (int)((idx / L_SEQ) % COMB);
    int b = (int)(idx / ((size_t)L_SEQ * COMB));
    float v;
    if (c < IN_IMG) {
        v = x[((size_t)(b * IN_IMG + c)) * L_SEQ + l];
    } else if (c == IN_IMG) {
        int w = l & 15;
        v = -0.3f + 0.6f * (float)w / 15.0f;
    } else if (c == IN_IMG + 1) {
        int h = l >> 4;
        v = -0.3f + 0.6f * (float)h / 15.0f;
    } else {
        v = pc[b * IN_PC + (c - IN_IMG - 2)];
    }
    g_comb[((size_t)(b * COMB + c)) * L_SEQ + l] = v;
    g_seq[((size_t)(b * L_SEQ + l)) * D_MODEL + c] = v;
}

// ----------------------------------------------------------------------------
__global__ void pool_avg_kernel() {
    __shared__ float s[32][257];
    int b  = blockIdx.y;
    int c0 = blockIdx.x * 32;
    int tid = threadIdx.x;
    for (int i = tid; i < 32 * 256; i += 256) {
        int cl = i >> 8, l = i & 255;
        int c = c0 + cl;
        s[cl][l] = (c < COMB) ? g_comb[((size_t)(b * COMB + c)) * L_SEQ + l] : 0.f;
    }
    __syncthreads();
    for (int oidx = tid; oidx < 275 * 32; oidx += 256) {
        int cl = oidx & 31;
        int q  = oidx >> 5;
        int sdim, qb, base;
        if (q < 25)       { sdim = 5;  qb = q;       base = POOL5_OFF;  }
        else if (q < 106) { sdim = 9;  qb = q - 25;  base = POOL9_OFF;  }
        else              { sdim = 13; qb = q - 106; base = POOL13_OFF; }
        int o = qb / sdim, p = qb % sdim;
        int h0 = (o * 16) / sdim, h1 = ((o + 1) * 16 + sdim - 1) / sdim;
        int w0 = (p * 16) / sdim, w1 = ((p + 1) * 16 + sdim - 1) / sdim;
        float sum = 0.f;
        for (int h = h0; h < h1; h++)
            for (int w = w0; w < w1; w++)
                sum += s[cl][h * 16 + w];
        sum *= 1.0f / (float)((h1 - h0) * (w1 - w0));
        int c = c0 + cl;
        if (c < COMB)
            g_pooled[((size_t)(base + b * sdim * sdim + qb)) * COMB + c] = sum;
    }
}

// ----------------------------------------------------------------------------
__global__ void pool0_mean_kernel() {
    int b = blockIdx.x;
    int d = threadIdx.x;
    float s = 0.f;
    for (int l = 0; l < L_SEQ; l++)
        s += g_p0[((size_t)(b * L_SEQ + l)) * DIM + d];
    g_y0[b * DIM + d] = s * (1.0f / (float)L_SEQ);
}

// ----------------------------------------------------------------------------
__global__ void fill_pool_cols_kernel() {
    int m = blockIdx.x;
    int t = threadIdx.x;
    int b = m >> 8, l = m & 255;
    int h = l >> 4, w = l & 15;
    int si = t >> 7, d = t & 127;
    float v;
    if (si == 0) {
        v = g_y0[b * DIM + d];
    } else {
        int sdim = (si == 1) ? 5 : (si == 2) ? 9 : 13;
        int base = (si == 1) ? POOL5_OFF : (si == 2) ? POOL9_OFF : POOL13_OFF;
        float sh = (h + 0.5f) * (float)sdim / 16.0f - 0.5f;
        sh = fminf(fmaxf(sh, 0.f), (float)sdim - 1.f);
        int h0 = (int)sh;
        int h1 = min(h0 + 1, sdim - 1);
        float fh = sh - (float)h0;
        float sw = (w + 0.5f) * (float)sdim / 16.0f - 0.5f;
        sw = fminf(fmaxf(sw, 0.f), (float)sdim - 1.f);
        int w0 = (int)sw;
        int w1 = min(w0 + 1, sdim - 1);
        float fw = sw - (float)w0;
        const float* Y = g_ys + (size_t)(base + b * sdim * sdim) * DIM;
        float v00 = Y[(size_t)(h0 * sdim + w0) * DIM + d];
        float v01 = Y[(size_t)(h0 * sdim + w1) * DIM + d];
        float v10 = Y[(size_t)(h1 * sdim + w0) * DIM + d];
        float v11 = Y[(size_t)(h1 * sdim + w1) * DIM + d];
        v = (1.f - fh) * ((1.f - fw) * v00 + fw * v01)
          +        fh  * ((1.f - fw) * v10 + fw * v11);
    }
    g_seq[(size_t)m * D_MODEL + COMB + t] = v;
}

// ----------------------------------------------------------------------------
__global__ void conv1d_silu_kernel(const float* __restrict__ w,
                                   const float* __restrict__ bias) {
    int d = blockIdx.x * 256 + threadIdx.x;
    int m = blockIdx.y;
    if (d >= D_INNER) return;
    int b = m >> 8, l = m & 255;
    float acc = bias[d];
    #pragma unroll
    for (int k = 0; k < D_CONV; k++) {
        int ls = l + k - (D_CONV - 1);
        if (ls >= 0)
            acc += w[d * D_CONV + k] * g_xz[((size_t)(b * L_SEQ + ls)) * (2 * D_INNER) + d];
    }
    float sg = 1.f / (1.f + __expf(-acc));
    g_uact[(size_t)m * D_INNER + d] = acc * sg;
}

// ----------------------------------------------------------------------------
__global__ __launch_bounds__(256)
void scan_kernel(const float* __restrict__ A_log, const float* __restrict__ Dp) {
    __shared__ float sB[L_SEQ][D_STATE];
    __shared__ float sC[L_SEQ][D_STATE];
    int b = blockIdx.y;
    int d = blockIdx.x * 256 + threadIdx.x;
    int tid = threadIdx.x;
    for (int i = tid; i < L_SEQ * D_STATE; i += 256) {
        int l = i >> 4, n = i & 15;
        const float* row = g_dbl + (size_t)(b * L_SEQ + l) * XPROJ_N;
        sB[l][n] = row[DT_RANK + n];
        sC[l][n] = row[DT_RANK + D_STATE + n];
    }
    __syncthreads();
    if (d >= D_INNER) return;

    float Ad[D_STATE];
    #pragma unroll
    for (int n = 0; n < D_STATE; n++) Ad[n] = -expf(A_log[d * D_STATE + n]);
    float Dd = Dp[d];
    float h[D_STATE];
    #pragma unroll
    for (int n = 0; n < D_STATE; n++) h[n] = 0.f;

    for (int l = 0; l < L_SEQ; l++) {
        size_t m = (size_t)(b * L_SEQ + l);
        float dt = g_dt[m * D_INNER + d];
        float u  = g_uact[m * D_INNER + d];
        float z  = g_xz[m * (2 * D_INNER) + D_INNER + d];
        float dtu = dt * u;
        float y = 0.f;
        #pragma unroll
        for (int n = 0; n < D_STATE; n++) {
            float dA = __expf(dt * Ad[n]);
            h[n] = dA * h[n] + dtu * sB[l][n];
            y = fmaf(h[n], sC[l][n], y);
        }
        float sig = 1.f / (1.f + __expf(-z));
        g_y[m * D_INNER + d] = (y + u * Dd) * (z * sig);
    }
}

// ----------------------------------------------------------------------------
extern "C" void kernel_launch(void* const* d_in, const int* in_sizes, int n_in,
                              void* d_out, int out_size) {
    const float* x          = (const float*)d_in[0];
    const float* pc_emb     = (const float*)d_in[1];
    const float* conv_w     = (const float*)d_in[2];
    const float* bn_gamma   = (const float*)d_in[3];
    const float* bn_beta    = (const float*)d_in[4];
    const float* bn_mean    = (const float*)d_in[5];
    const float* bn_var     = (const float*)d_in[6];
    const float* in_proj_w  = (const float*)d_in[7];
    const float* conv1d_w   = (const float*)d_in[8];
    const float* conv1d_b   = (const float*)d_in[9];
    const float* x_proj_w   = (const float*)d_in[10];
    const float* dt_proj_w  = (const float*)d_in[11];
    const float* dt_proj_b  = (const float*)d_in[12];
    const float* A_log      = (const float*)d_in[13];
    const float* Dp         = (const float*)d_in[14];
    const float* out_proj_w = (const float*)d_in[15];
    float* out = (float*)d_out;

    float *p_seq, *p_xz, *p_uact, *p_dbl, *p_dt, *p_y, *p_p0, *p_pooled, *p_ys;
    float *p_bninv, *p_bnbias;
    cudaGetSymbolAddress((void**)&p_seq,    g_seq);
    cudaGetSymbolAddress((void**)&p_xz,     g_xz);
    cudaGetSymbolAddress((void**)&p_uact,   g_uact);
    cudaGetSymbolAddress((void**)&p_dbl,    g_dbl);
    cudaGetSymbolAddress((void**)&p_dt,     g_dt);
    cudaGetSymbolAddress((void**)&p_y,      g_y);
    cudaGetSymbolAddress((void**)&p_p0,     g_p0);
    cudaGetSymbolAddress((void**)&p_pooled, g_pooled);
    cudaGetSymbolAddress((void**)&p_ys,     g_ys);
    cudaGetSymbolAddress((void**)&p_bninv,  g_bninv);
    cudaGetSymbolAddress((void**)&p_bnbias, g_bnbias);

    // 1) BN fold
    prep_bn_kernel<<<2, 256>>>(bn_gamma, bn_beta, bn_mean, bn_var);

    // 2) build comb (both layouts)
    {
        size_t total = (size_t)BATCH * COMB * L_SEQ;
        build_comb_kernel<<<(unsigned)((total + 255) / 256), 256>>>(x, pc_emb);
    }

    // 3) adaptive pools for scales 5/9/13
    pool_avg_kernel<<<dim3(25, BATCH), 256>>>();

    // 4) conv0 full-res (HMMA, BN+ReLU6)
    mma_gemm_kernel<4><<<dim3(1, M_TOTAL / 128), 256>>>(
        p_seq, D_MODEL, conv_w, COMB, p_p0, DIM,
        M_TOTAL, DIM, COMB, p_bninv, p_bnbias);

    // 5) pool0 mean
    pool0_mean_kernel<<<BATCH, DIM>>>();

    // 6) pooled-branch convs (HMMA, BN+ReLU6)
    {
        const int sM[3]   = {1600, 5184, 10816};
        const int sOff[3] = {POOL5_OFF, POOL9_OFF, POOL13_OFF};
        for (int i = 0; i < 3; i++) {
            int pool = i + 1;
            mma_gemm_kernel<4><<<dim3(1, (sM[i] + 127) / 128), 256>>>(
                p_pooled + (size_t)sOff[i] * COMB, COMB,
                conv_w + (size_t)pool * DIM * COMB, COMB,
                p_ys + (size_t)sOff[i] * DIM, DIM,
                sM[i], DIM, COMB,
                p_bninv + pool * DIM, p_bnbias + pool * DIM);
        }
    }

    // 7) fill pool columns of seq
    fill_pool_cols_kernel<<<M_TOTAL, 512>>>();

    // 8) in_proj (HMMA) -> g_xz
    mma_gemm_kernel<0><<<dim3((2 * D_INNER + 127) / 128, M_TOTAL / 128), 256>>>(
        p_seq, D_MODEL, in_proj_w, D_MODEL, p_xz, 2 * D_INNER,
        M_TOTAL, 2 * D_INNER, D_MODEL, nullptr, nullptr);

    // 9) depthwise causal conv1d + SiLU
    conv1d_silu_kernel<<<dim3((D_INNER + 255) / 256, M_TOTAL), 256>>>(conv1d_w, conv1d_b);

    // 10) x_proj (HMMA) -> g_dbl
    mma_gemm_kernel<0><<<dim3(1, M_TOTAL / 128), 256>>>(
        p_uact, D_INNER, x_proj_w, D_INNER, p_dbl, XPROJ_N,
        M_TOTAL, XPROJ_N, D_INNER, nullptr, nullptr);

    // 11) dt_proj (HMMA, softplus) -> g_dt   (A = first 81 cols of g_dbl)
    mma_gemm_kernel<3><<<dim3((D_INNER + 127) / 128, M_TOTAL / 128), 256>>>(
        p_dbl, XPROJ_N, dt_proj_w, DT_RANK, p_dt, D_INNER,
        M_TOTAL, D_INNER, DT_RANK, nullptr, dt_proj_b);

    // 12) selective scan (fused output gate)
    scan_kernel<<<dim3((D_INNER + 255) / 256, BATCH), 256>>>(A_log, Dp);

    // 13) out_proj (HMMA, fused transpose) -> out
    mma_gemm_kernel<1><<<dim3((D_MODEL + 127) / 128, M_TOTAL / 128), 256>>>(
        p_y, D_INNER, out_proj_w, D_INNER, out, 0,
        M_TOTAL, D_MODEL, D_INNER, nullptr, nullptr);
}